// round 13
// baseline (speedup 1.0000x reference)
#include <cuda_runtime.h>
#include <cuda_bf16.h>
#include <math.h>
#include <stdint.h>

// ---------------- problem dims ----------------
#define NB   131072
#define A_D  17
#define M_D  5

#define K1   376      // state dim
#define N1   400
#define N2   300
#define K1P  384      // 12 chunks of 32
#define K2P  416      // 13 chunks
#define K3P  320      // 10 chunks

#define EPIS_MIN 4.53999297624848e-05f
#define EPIS_MAX 7.38905609893065f
#define HALF_D_LOG2PI 15.6219550644794f

// ---------------- scratch (__device__ globals; zero-initialized at load) ----------------
__device__ __align__(16) __nv_bfloat16 g_shi[(size_t)NB * K1P];   // split state
__device__ __align__(16) __nv_bfloat16 g_slo[(size_t)NB * K1P];
__device__ __align__(16) __nv_bfloat16 g_h1hi[(size_t)NB * K2P];
__device__ __align__(16) __nv_bfloat16 g_h1lo[(size_t)NB * K2P];
__device__ __align__(16) __nv_bfloat16 g_h2hi[(size_t)NB * K3P];
__device__ __align__(16) __nv_bfloat16 g_h2lo[(size_t)NB * K3P];
__device__ __align__(16) float g_z3[(size_t)NB * 256];

// weights, transposed + split: [N_alloc][K_pad], zero-padded
__device__ __align__(16) __nv_bfloat16 g_w1hi[512 * K1P], g_w1lo[512 * K1P];
__device__ __align__(16) __nv_bfloat16 g_w2hi[384 * K2P], g_w2lo[384 * K2P];
__device__ __align__(16) __nv_bfloat16 g_w3hi[256 * K3P], g_w3lo[256 * K3P];

#define W1_TOT (512 * K1P)
#define W2_TOT (384 * K2P)
#define W3_TOT (256 * K3P)

// ---------------- helpers ----------------
__device__ __forceinline__ uint32_t smem_u32(const void* p) {
    uint32_t a;
    asm("{ .reg .u64 t; cvta.to.shared.u64 t, %1; cvt.u32.u64 %0, t; }" : "=r"(a) : "l"(p));
    return a;
}

__device__ __forceinline__ void ldsm4(uint32_t* r, uint32_t addr) {
    asm volatile("ldmatrix.sync.aligned.m8n8.x4.shared.b16 {%0,%1,%2,%3}, [%4];"
                 : "=r"(r[0]), "=r"(r[1]), "=r"(r[2]), "=r"(r[3]) : "r"(addr));
}

__device__ __forceinline__ void mma_bf16(float* c, const uint32_t* a, const uint32_t* b) {
    asm volatile("mma.sync.aligned.m16n8k16.row.col.f32.bf16.bf16.f32 "
                 "{%0,%1,%2,%3}, {%4,%5,%6,%7}, {%8,%9}, {%0,%1,%2,%3};"
                 : "+f"(c[0]), "+f"(c[1]), "+f"(c[2]), "+f"(c[3])
                 : "r"(a[0]), "r"(a[1]), "r"(a[2]), "r"(a[3]), "r"(b[0]), "r"(b[1]));
}

__device__ __forceinline__ void cp16(uint32_t dst, const void* src) {
    asm volatile("cp.async.cg.shared.global [%0], [%1], 16;"
                 :: "r"(dst), "l"(src) : "memory");
}
#define CP_COMMIT() asm volatile("cp.async.commit_group;" ::: "memory")
#define CP_WAIT0()  asm volatile("cp.async.wait_group 0;" ::: "memory")

__device__ __forceinline__ void split_bf16(float x, __nv_bfloat16& h, __nv_bfloat16& l) {
    h = __float2bfloat16_rn(x);
    l = __float2bfloat16_rn(x - __bfloat162float(h));
}
__device__ __forceinline__ uint32_t pack_us(__nv_bfloat16 a, __nv_bfloat16 b) {
    return (uint32_t)__bfloat16_as_ushort(a) | ((uint32_t)__bfloat16_as_ushort(b) << 16);
}

// XOR swizzle: 16B chunk c (0..3) of row r at phys chunk c ^ ((r>>1)&3); 64B pitch.
__device__ __forceinline__ uint32_t swz(int r, int c) {
    return (uint32_t)(r * 64 + ((c ^ ((r >> 1) & 3)) << 4));
}

// ---------------- weight prep (single launch): transpose + bf16 hi/lo split ----------------
__global__ void split_w_all(const float* __restrict__ W1, const float* __restrict__ W2,
                            const float* __restrict__ W3,
                            __nv_bfloat16* __restrict__ w1h, __nv_bfloat16* __restrict__ w1l,
                            __nv_bfloat16* __restrict__ w2h, __nv_bfloat16* __restrict__ w2l,
                            __nv_bfloat16* __restrict__ w3h, __nv_bfloat16* __restrict__ w3l)
{
    int idx = blockIdx.x * blockDim.x + threadIdx.x;
    const float* W; __nv_bfloat16 *Hh, *Hl;
    int K, N, Kp, loc;
    if (idx < W1_TOT) {
        W = W1; Hh = w1h; Hl = w1l; K = K1; N = N1; Kp = K1P; loc = idx;
    } else if (idx < W1_TOT + W2_TOT) {
        W = W2; Hh = w2h; Hl = w2l; K = N1; N = N2; Kp = K2P; loc = idx - W1_TOT;
    } else if (idx < W1_TOT + W2_TOT + W3_TOT) {
        W = W3; Hh = w3h; Hl = w3l; K = N2; N = 255; Kp = K3P; loc = idx - W1_TOT - W2_TOT;
    } else return;
    int n = loc / Kp;
    int k = loc - n * Kp;
    float v = (k < K && n < N) ? W[(size_t)k * N + n] : 0.f;
    __nv_bfloat16 h, l;
    split_bf16(v, h, l);
    Hh[loc] = h;
    Hl[loc] = l;
}

// ---------------- activation prep: fp32 state -> bf16 hi/lo, zero-padded ----------------
__global__ void split_act(const float* __restrict__ X, __nv_bfloat16* __restrict__ Hh,
                          __nv_bfloat16* __restrict__ Hl)
{
    int idx = blockIdx.x * blockDim.x + threadIdx.x;   // one per 4 elements
    size_t i4 = (size_t)idx * 4;
    if (i4 >= (size_t)NB * K1P) return;
    int row = (int)(i4 / K1P);
    int k   = (int)(i4 - (size_t)row * K1P);
    uint2 hw = make_uint2(0u, 0u), lw = hw;
    if (k < K1) {   // K1 % 4 == 0, so full float4 or none
        float4 v = *(const float4*)(X + (size_t)row * K1 + k);
        __nv_bfloat16 h0,l0,h1,l1,h2,l2,h3,l3;
        split_bf16(v.x,h0,l0); split_bf16(v.y,h1,l1);
        split_bf16(v.z,h2,l2); split_bf16(v.w,h3,l3);
        hw.x = pack_us(h0,h1); hw.y = pack_us(h2,h3);
        lw.x = pack_us(l0,l1); lw.y = pack_us(l2,l3);
    }
    *(uint2*)(Hh + i4) = hw;
    *(uint2*)(Hl + i4) = lw;
}

// ---------------- bf16x3 mma GEMM (small-CTA variant) ----------------
// BM=64, BN=64, BK=32; 4 warps as 2(row)x2(col); warp tile 32x32 (unchanged body).
// 2-stage cp.async pipeline (lookahead 1), XOR-swizzled 64B-pitch smem, no guards.
// 6 CTAs/SM (24 warps) — cross-CTA overlap replaces deeper intra-CTA pipelining;
// 4-warp barriers minimize convergence spread.
#define AHI_O  0
#define ALO_O  4096
#define BHI_O  8192
#define BLO_O  12288
#define ST_SZ  16384
#define SMEM_TOT (2 * ST_SZ)

template<int OUT_BF16, int NCH, int NKS, int NN, int NBIAS, int SC>
__global__ __launch_bounds__(128, 6)
void mma_gemm(const __nv_bfloat16* __restrict__ Ah, const __nv_bfloat16* __restrict__ Al,
              const __nv_bfloat16* __restrict__ Bh, const __nv_bfloat16* __restrict__ Bl,
              const float* __restrict__ bias,
              float* __restrict__ Cf, __nv_bfloat16* __restrict__ Ch, __nv_bfloat16* __restrict__ Cl)
{
    constexpr int KP = NCH * 32;     // padded K stride of A and B

    extern __shared__ char smem[];
    const uint32_t sb = smem_u32(smem);
    const int tid  = threadIdx.x;
    const int lane = tid & 31;
    const int wid  = tid >> 5;
    const int wrow = wid & 1;        // 0..1 : 32-row group
    const int wcol = wid >> 1;       // 0..1 : 32-col group
    const int row0 = blockIdx.y * 64;
    const int col0 = blockIdx.x * 64;
    const int extw = (NN - col0) - wcol * 32;
    const int live_nt = max(0, min(4, (extw + 7) >> 3));

    float acc[2][4][4];
    #pragma unroll
    for (int i = 0; i < 2; i++)
        #pragma unroll
        for (int j = 0; j < 4; j++)
            #pragma unroll
            for (int q = 0; q < 4; q++) acc[i][j][q] = 0.f;

    // loader: 128 threads; row = tid>>1 (0..63), half = tid&1; 4 A + 4 B cp16/thread.
    const int lrow = tid >> 1;
    const int lhf  = tid & 1;
    const __nv_bfloat16* pAh = Ah + (size_t)(row0 + lrow) * KP + lhf * 16;
    const __nv_bfloat16* pAl = Al + (size_t)(row0 + lrow) * KP + lhf * 16;
    const __nv_bfloat16* pBh = Bh + (size_t)(col0 + lrow) * KP + lhf * 16;
    const __nv_bfloat16* pBl = Bl + (size_t)(col0 + lrow) * KP + lhf * 16;
    const uint32_t s0 = swz(lrow, lhf * 2);
    const uint32_t s1 = swz(lrow, lhf * 2 + 1);

    auto load_chunk = [&](int c, int s) {
        const uint32_t stb = sb + s * ST_SZ;
        cp16(stb + s0 + AHI_O, pAh + c * 32);
        cp16(stb + s1 + AHI_O, pAh + c * 32 + 8);
        cp16(stb + s0 + ALO_O, pAl + c * 32);
        cp16(stb + s1 + ALO_O, pAl + c * 32 + 8);
        cp16(stb + s0 + BHI_O, pBh + c * 32);
        cp16(stb + s1 + BHI_O, pBh + c * 32 + 8);
        cp16(stb + s0 + BLO_O, pBl + c * 32);
        cp16(stb + s1 + BLO_O, pBl + c * 32 + 8);
    };

    // compute-side swizzled offsets (loop-invariant parts hoisted)
    const int bn_row = wcol * 32 + (lane & 7) + ((lane >> 4) << 3);
    const int b_c2   = (lane >> 3) & 1;
    const int ar_row = wrow * 32 + (lane & 15);
    const int a_c2   = lane >> 4;

    auto compute_ks = [&](uint32_t stb, int ks) {
        uint32_t bh[8], bl[8];
        #pragma unroll
        for (int p = 0; p < 2; ++p) {
            uint32_t off = swz(bn_row + p * 16, ks * 2 + b_c2);
            ldsm4(&bh[p * 4], stb + BHI_O + off);
            ldsm4(&bl[p * 4], stb + BLO_O + off);
        }
        #pragma unroll
        for (int mt = 0; mt < 2; ++mt) {
            uint32_t off = swz(ar_row + mt * 16, ks * 2 + a_c2);
            uint32_t ah[4], al[4];
            ldsm4(ah, stb + AHI_O + off);
            ldsm4(al, stb + ALO_O + off);
            #pragma unroll
            for (int nt = 0; nt < 4; ++nt) {
                if (nt < live_nt) {
                    mma_bf16(acc[mt][nt], ah, &bh[nt * 2]);
                    mma_bf16(acc[mt][nt], ah, &bl[nt * 2]);
                    mma_bf16(acc[mt][nt], al, &bh[nt * 2]);
                }
            }
        }
    };

    // prologue: chunk 0 into stage 0
    load_chunk(0, 0); CP_COMMIT();

    #pragma unroll
    for (int c = 0; c < NCH; ++c) {
        CP_WAIT0();            // all issued loads done (chunk c resident)
        __syncthreads();       // chunk c visible to all; compute(c-1) done everywhere

        if (c + 1 < NCH) load_chunk(c + 1, (c + 1) & 1);   // stage held chunk c-1 (done)
        CP_COMMIT();

        const uint32_t stb = sb + (c & 1) * ST_SZ;
        if (2 * c < NKS) compute_ks(stb, 0);
        if (2 * c + 1 < NKS) compute_ks(stb, 1);           // NKS trims dead ks blocks
    }

    // ---- store ----
    #pragma unroll
    for (int mt = 0; mt < 2; ++mt) {
        int r0 = row0 + wrow * 32 + mt * 16 + (lane >> 2);
        int r1 = r0 + 8;
        #pragma unroll
        for (int nt = 0; nt < 4; ++nt) {
            int col = col0 + wcol * 32 + nt * 8 + (lane & 3) * 2;
            if (OUT_BF16) {
                if (col < NN) {
                    float b0 = bias[col], b1 = bias[col + 1];
                    float v00 = fmaxf(acc[mt][nt][0] + b0, 0.f);
                    float v01 = fmaxf(acc[mt][nt][1] + b1, 0.f);
                    float v10 = fmaxf(acc[mt][nt][2] + b0, 0.f);
                    float v11 = fmaxf(acc[mt][nt][3] + b1, 0.f);
                    __nv_bfloat16 h0, l0, h1, l1;
                    split_bf16(v00, h0, l0); split_bf16(v01, h1, l1);
                    *(uint32_t*)(Ch + (size_t)r0 * SC + col) = pack_us(h0, h1);
                    *(uint32_t*)(Cl + (size_t)r0 * SC + col) = pack_us(l0, l1);
                    split_bf16(v10, h0, l0); split_bf16(v11, h1, l1);
                    *(uint32_t*)(Ch + (size_t)r1 * SC + col) = pack_us(h0, h1);
                    *(uint32_t*)(Cl + (size_t)r1 * SC + col) = pack_us(l0, l1);
                }
            } else {
                float b0 = (col < NBIAS) ? bias[col] : 0.f;
                float b1 = (col + 1 < NBIAS) ? bias[col + 1] : 0.f;
                float2 p0 = make_float2(acc[mt][nt][0] + b0, acc[mt][nt][1] + b1);
                float2 p1 = make_float2(acc[mt][nt][2] + b0, acc[mt][nt][3] + b1);
                *(float2*)(Cf + (size_t)r0 * SC + col) = p0;
                *(float2*)(Cf + (size_t)r1 * SC + col) = p1;
            }
        }
    }
}

// ---------------- math epilogue ----------------
__device__ __forceinline__ float fast_tanh(float x)
{
    float ax = fabsf(x);
    float e  = __expf(-2.f * ax);
    float t  = __fdividef(1.f - e, 1.f + e);
    return copysignf(t, x);
}

__global__ __launch_bounds__(256)
void epilogue_kernel(const float* __restrict__ z3, const float* __restrict__ eps,
                     float* __restrict__ out)
{
    int gwarp = (blockIdx.x * blockDim.x + threadIdx.x) >> 5;
    int lane  = threadIdx.x & 31;
    if (gwarp >= NB) return;

    const float* L = z3 + (size_t)gwarp * 256;

    float term_ttl = 0.f, term_eps = 0.f, corr = 0.f;

    if (lane < A_D) {
        int a = lane;
        float mw[M_D], mm[M_D], lms[M_D];
        #pragma unroll
        for (int m = 0; m < M_D; m++) {
            mw[m]  = fast_tanh(L[a * M_D + m]);
            mm[m]  = fast_tanh(L[85 + a * M_D + m]);
            lms[m] = fast_tanh(L[170 + a * M_D + m]);
        }
        float mx = mw[0];
        #pragma unroll
        for (int m = 1; m < M_D; m++) mx = fmaxf(mx, mw[m]);
        float e[M_D], se = 0.f;
        #pragma unroll
        for (int m = 0; m < M_D; m++) { e[m] = __expf(mw[m] - mx); se += e[m]; }
        float inv = __fdividef(1.f, se);

        float mean = 0.f, alea = 0.f;
        float w[M_D];
        #pragma unroll
        for (int m = 0; m < M_D; m++) {
            w[m]  = e[m] * inv;
            mean += w[m] * mm[m];
            float lc = fminf(fmaxf(lms[m], -10.f), 2.f);
            alea += w[m] * __expf(lc);
        }
        float epis = 0.f;
        #pragma unroll
        for (int m = 0; m < M_D; m++) {
            float dd = mm[m] - mean;
            epis += w[m] * dd * dd;
        }
        epis = fminf(fmaxf(epis, EPIS_MIN), EPIS_MAX);
        float total = alea + epis;

        float ev = eps[(size_t)gwarp * A_D + a];
        float x  = mean + total * ev;
        float th = fast_tanh(x);
        out[(size_t)gwarp * A_D + a] = th;

        float d  = x - mean;
        float zt = __fdividef(d, total);
        float ze = __fdividef(d, epis);
        term_ttl = zt * zt + 2.f * __logf(total);
        term_eps = ze * ze + 2.f * __logf(epis);
        corr     = __logf(1.f - th * th + 1e-6f);
    }

    #pragma unroll
    for (int off = 16; off > 0; off >>= 1) {
        term_ttl += __shfl_down_sync(0xffffffffu, term_ttl, off);
        term_eps += __shfl_down_sync(0xffffffffu, term_eps, off);
        corr     += __shfl_down_sync(0xffffffffu, corr, off);
    }

    if (lane == 0) {
        float lp_ttl = -0.5f * term_ttl - HALF_D_LOG2PI;
        float lp_eps = -0.5f * term_eps - HALF_D_LOG2PI;
        out[(size_t)NB * A_D + gwarp]       = lp_ttl - corr;
        out[(size_t)NB * (A_D + 1) + gwarp] = lp_eps - corr;
    }
}

// ---------------- launch ----------------
extern "C" void kernel_launch(void* const* d_in, const int* in_sizes, int n_in,
                              void* d_out, int out_size)
{
    (void)in_sizes; (void)n_in; (void)out_size;
    const float* state = (const float*)d_in[0];
    const float* eps   = (const float*)d_in[1];
    const float* W1    = (const float*)d_in[2];
    const float* b1    = (const float*)d_in[3];
    const float* W2    = (const float*)d_in[4];
    const float* b2    = (const float*)d_in[5];
    const float* W3    = (const float*)d_in[6];
    const float* b3    = (const float*)d_in[7];
    float* out = (float*)d_out;

    void *p;
    cudaGetSymbolAddress(&p, g_shi);  __nv_bfloat16* shh = (__nv_bfloat16*)p;
    cudaGetSymbolAddress(&p, g_slo);  __nv_bfloat16* shl = (__nv_bfloat16*)p;
    cudaGetSymbolAddress(&p, g_h1hi); __nv_bfloat16* h1h = (__nv_bfloat16*)p;
    cudaGetSymbolAddress(&p, g_h1lo); __nv_bfloat16* h1l = (__nv_bfloat16*)p;
    cudaGetSymbolAddress(&p, g_h2hi); __nv_bfloat16* h2h = (__nv_bfloat16*)p;
    cudaGetSymbolAddress(&p, g_h2lo); __nv_bfloat16* h2l = (__nv_bfloat16*)p;
    cudaGetSymbolAddress(&p, g_z3);   float* z3 = (float*)p;
    cudaGetSymbolAddress(&p, g_w1hi); __nv_bfloat16* w1h = (__nv_bfloat16*)p;
    cudaGetSymbolAddress(&p, g_w1lo); __nv_bfloat16* w1l = (__nv_bfloat16*)p;
    cudaGetSymbolAddress(&p, g_w2hi); __nv_bfloat16* w2h = (__nv_bfloat16*)p;
    cudaGetSymbolAddress(&p, g_w2lo); __nv_bfloat16* w2l = (__nv_bfloat16*)p;
    cudaGetSymbolAddress(&p, g_w3hi); __nv_bfloat16* w3h = (__nv_bfloat16*)p;
    cudaGetSymbolAddress(&p, g_w3lo); __nv_bfloat16* w3l = (__nv_bfloat16*)p;

    auto g1 = mma_gemm<1, 12, 24, N1, N1, K2P>;   // K=376 -> 24 live ks of 24
    auto g2 = mma_gemm<1, 13, 25, N2, N2, K3P>;   // K=400 -> 25 live ks of 26
    auto g3 = mma_gemm<0, 10, 19, 256, 255, 256>; // K=300 -> 19 live ks of 20
    cudaFuncSetAttribute(g1, cudaFuncAttributeMaxDynamicSharedMemorySize, SMEM_TOT);
    cudaFuncSetAttribute(g2, cudaFuncAttributeMaxDynamicSharedMemorySize, SMEM_TOT);
    cudaFuncSetAttribute(g3, cudaFuncAttributeMaxDynamicSharedMemorySize, SMEM_TOT);

    int wtot = W1_TOT + W2_TOT + W3_TOT;
    split_w_all<<<(wtot + 255) / 256, 256>>>(W1, W2, W3, w1h, w1l, w2h, w2l, w3h, w3l);
    split_act<<<((size_t)NB * K1P / 4 + 255) / 256, 256>>>(state, shh, shl);

    dim3 blk(128);
    // index 3 = g2 for ncu visibility; grids: BM=64 -> grid.y = NB/64 = 2048
    g1<<<dim3(7, NB/64), blk, SMEM_TOT>>>(shh, shl, w1h, w1l, b1, nullptr, h1h, h1l);
    g2<<<dim3(5, NB/64), blk, SMEM_TOT>>>(h1h, h1l, w2h, w2l, b2, nullptr, h2h, h2l);
    g3<<<dim3(4, NB/64), blk, SMEM_TOT>>>(h2h, h2l, w3h, w3l, b3, z3, nullptr, nullptr);

    epilogue_kernel<<<NB/8, 256>>>(z3, eps, out);
}

// round 14
// speedup vs baseline: 1.1629x; 1.1629x over previous
#include <cuda_runtime.h>
#include <cuda_bf16.h>
#include <math.h>
#include <stdint.h>

// ---------------- problem dims ----------------
#define NB   131072
#define A_D  17
#define M_D  5

#define K1   376      // state dim
#define N1   400
#define N2   300
#define K1P  384      // 12 chunks of 32
#define K2P  416      // 13 chunks
#define K3P  320      // 10 chunks

#define EPIS_MIN 4.53999297624848e-05f
#define EPIS_MAX 7.38905609893065f
#define HALF_D_LOG2PI 15.6219550644794f

// ---------------- scratch (__device__ globals; zero-initialized at load) ----------------
__device__ __align__(16) __nv_bfloat16 g_shi[(size_t)NB * K1P];   // split state
__device__ __align__(16) __nv_bfloat16 g_slo[(size_t)NB * K1P];
__device__ __align__(16) __nv_bfloat16 g_h1hi[(size_t)NB * K2P];
__device__ __align__(16) __nv_bfloat16 g_h1lo[(size_t)NB * K2P];
__device__ __align__(16) __nv_bfloat16 g_h2hi[(size_t)NB * K3P];
__device__ __align__(16) __nv_bfloat16 g_h2lo[(size_t)NB * K3P];
__device__ __align__(16) float g_z3[(size_t)NB * 256];

// weights, transposed + split: [N_alloc][K_pad], zero-padded
__device__ __align__(16) __nv_bfloat16 g_w1hi[512 * K1P], g_w1lo[512 * K1P];
__device__ __align__(16) __nv_bfloat16 g_w2hi[384 * K2P], g_w2lo[384 * K2P];
__device__ __align__(16) __nv_bfloat16 g_w3hi[256 * K3P], g_w3lo[256 * K3P];

#define W1_TOT (512 * K1P)
#define W2_TOT (384 * K2P)
#define W3_TOT (256 * K3P)

// ---------------- helpers ----------------
__device__ __forceinline__ uint32_t smem_u32(const void* p) {
    uint32_t a;
    asm("{ .reg .u64 t; cvta.to.shared.u64 t, %1; cvt.u32.u64 %0, t; }" : "=r"(a) : "l"(p));
    return a;
}

__device__ __forceinline__ void ldsm4(uint32_t* r, uint32_t addr) {
    asm volatile("ldmatrix.sync.aligned.m8n8.x4.shared.b16 {%0,%1,%2,%3}, [%4];"
                 : "=r"(r[0]), "=r"(r[1]), "=r"(r[2]), "=r"(r[3]) : "r"(addr));
}

__device__ __forceinline__ void mma_bf16(float* c, const uint32_t* a, const uint32_t* b) {
    asm volatile("mma.sync.aligned.m16n8k16.row.col.f32.bf16.bf16.f32 "
                 "{%0,%1,%2,%3}, {%4,%5,%6,%7}, {%8,%9}, {%0,%1,%2,%3};"
                 : "+f"(c[0]), "+f"(c[1]), "+f"(c[2]), "+f"(c[3])
                 : "r"(a[0]), "r"(a[1]), "r"(a[2]), "r"(a[3]), "r"(b[0]), "r"(b[1]));
}

__device__ __forceinline__ void cp16(uint32_t dst, const void* src) {
    asm volatile("cp.async.cg.shared.global [%0], [%1], 16;"
                 :: "r"(dst), "l"(src) : "memory");
}
#define CP_COMMIT() asm volatile("cp.async.commit_group;" ::: "memory")
#define CP_WAIT1()  asm volatile("cp.async.wait_group 1;" ::: "memory")

__device__ __forceinline__ void split_bf16(float x, __nv_bfloat16& h, __nv_bfloat16& l) {
    h = __float2bfloat16_rn(x);
    l = __float2bfloat16_rn(x - __bfloat162float(h));
}
__device__ __forceinline__ uint32_t pack_us(__nv_bfloat16 a, __nv_bfloat16 b) {
    return (uint32_t)__bfloat16_as_ushort(a) | ((uint32_t)__bfloat16_as_ushort(b) << 16);
}

// XOR swizzle: 16B chunk c (0..3) of row r at phys chunk c ^ ((r>>1)&3); 64B pitch.
__device__ __forceinline__ uint32_t swz(int r, int c) {
    return (uint32_t)(r * 64 + ((c ^ ((r >> 1) & 3)) << 4));
}

// ---------------- weight prep (single launch): transpose + bf16 hi/lo split ----------------
__global__ void split_w_all(const float* __restrict__ W1, const float* __restrict__ W2,
                            const float* __restrict__ W3,
                            __nv_bfloat16* __restrict__ w1h, __nv_bfloat16* __restrict__ w1l,
                            __nv_bfloat16* __restrict__ w2h, __nv_bfloat16* __restrict__ w2l,
                            __nv_bfloat16* __restrict__ w3h, __nv_bfloat16* __restrict__ w3l)
{
    int idx = blockIdx.x * blockDim.x + threadIdx.x;
    const float* W; __nv_bfloat16 *Hh, *Hl;
    int K, N, Kp, loc;
    if (idx < W1_TOT) {
        W = W1; Hh = w1h; Hl = w1l; K = K1; N = N1; Kp = K1P; loc = idx;
    } else if (idx < W1_TOT + W2_TOT) {
        W = W2; Hh = w2h; Hl = w2l; K = N1; N = N2; Kp = K2P; loc = idx - W1_TOT;
    } else if (idx < W1_TOT + W2_TOT + W3_TOT) {
        W = W3; Hh = w3h; Hl = w3l; K = N2; N = 255; Kp = K3P; loc = idx - W1_TOT - W2_TOT;
    } else return;
    int n = loc / Kp;
    int k = loc - n * Kp;
    float v = (k < K && n < N) ? W[(size_t)k * N + n] : 0.f;
    __nv_bfloat16 h, l;
    split_bf16(v, h, l);
    Hh[loc] = h;
    Hl[loc] = l;
}

// ---------------- activation prep: fp32 state -> bf16 hi/lo, zero-padded ----------------
__global__ void split_act(const float* __restrict__ X, __nv_bfloat16* __restrict__ Hh,
                          __nv_bfloat16* __restrict__ Hl)
{
    int idx = blockIdx.x * blockDim.x + threadIdx.x;   // one per 4 elements
    size_t i4 = (size_t)idx * 4;
    if (i4 >= (size_t)NB * K1P) return;
    int row = (int)(i4 / K1P);
    int k   = (int)(i4 - (size_t)row * K1P);
    uint2 hw = make_uint2(0u, 0u), lw = hw;
    if (k < K1) {   // K1 % 4 == 0, so full float4 or none
        float4 v = *(const float4*)(X + (size_t)row * K1 + k);
        __nv_bfloat16 h0,l0,h1,l1,h2,l2,h3,l3;
        split_bf16(v.x,h0,l0); split_bf16(v.y,h1,l1);
        split_bf16(v.z,h2,l2); split_bf16(v.w,h3,l3);
        hw.x = pack_us(h0,h1); hw.y = pack_us(h2,h3);
        lw.x = pack_us(l0,l1); lw.y = pack_us(l2,l3);
    }
    *(uint2*)(Hh + i4) = hw;
    *(uint2*)(Hl + i4) = lw;
}

// ---------------- bf16x3 mma GEMM (R12: fully templated / unrolled) ----------------
// BM=128, BN=64, BK=32; 8 warps as 4(row)x2(col); warp tile 32x32.
// 3-stage cp.async pipeline (lookahead 2), XOR-swizzled 64B-pitch smem, no guards.
// 3 CTAs/SM. NKS = ceil(K/16) skips all-zero trailing ks blocks at compile time.
#define AHI_O  0
#define ALO_O  8192
#define BHI_O  16384
#define BLO_O  20480
#define ST_SZ  24576
#define SMEM_TOT (3 * ST_SZ)

template<int OUT_BF16, int NCH, int NKS, int NN, int NBIAS, int SC>
__global__ __launch_bounds__(256, 3)
void mma_gemm(const __nv_bfloat16* __restrict__ Ah, const __nv_bfloat16* __restrict__ Al,
              const __nv_bfloat16* __restrict__ Bh, const __nv_bfloat16* __restrict__ Bl,
              const float* __restrict__ bias,
              float* __restrict__ Cf, __nv_bfloat16* __restrict__ Ch, __nv_bfloat16* __restrict__ Cl)
{
    constexpr int KP = NCH * 32;     // padded K stride of A and B

    extern __shared__ char smem[];
    const uint32_t sb = smem_u32(smem);
    const int tid  = threadIdx.x;
    const int lane = tid & 31;
    const int wid  = tid >> 5;
    const int wrow = wid & 3;        // 0..3 : 32-row group
    const int wcol = wid >> 2;       // 0..1 : 32-col group
    const int row0 = blockIdx.y * 128;
    const int col0 = blockIdx.x * 64;
    const int extw = (NN - col0) - wcol * 32;
    const int live_nt = max(0, min(4, (extw + 7) >> 3));

    float acc[2][4][4];
    #pragma unroll
    for (int i = 0; i < 2; i++)
        #pragma unroll
        for (int j = 0; j < 4; j++)
            #pragma unroll
            for (int q = 0; q < 4; q++) acc[i][j][q] = 0.f;

    // loader base pointers (chunk offset is a compile-time immediate per unroll step)
    const int arow = tid >> 1;
    const int ahf  = tid & 1;
    const int brow = tid >> 2;
    const int bq   = tid & 3;
    const __nv_bfloat16* pAh = Ah + (size_t)(row0 + arow) * KP + ahf * 16;
    const __nv_bfloat16* pAl = Al + (size_t)(row0 + arow) * KP + ahf * 16;
    const __nv_bfloat16* pBh = Bh + (size_t)(col0 + brow) * KP + bq * 8;
    const __nv_bfloat16* pBl = Bl + (size_t)(col0 + brow) * KP + bq * 8;
    const uint32_t sa0 = swz(arow, ahf * 2);
    const uint32_t sa1 = swz(arow, ahf * 2 + 1);
    const uint32_t sb0 = swz(brow, bq);

    auto load_chunk = [&](int c, int s) {
        const uint32_t stb = sb + s * ST_SZ;
        cp16(stb + sa0 + AHI_O, pAh + c * 32);
        cp16(stb + sa1 + AHI_O, pAh + c * 32 + 8);
        cp16(stb + sa0 + ALO_O, pAl + c * 32);
        cp16(stb + sa1 + ALO_O, pAl + c * 32 + 8);
        cp16(stb + sb0 + BHI_O, pBh + c * 32);
        cp16(stb + sb0 + BLO_O, pBl + c * 32);
    };

    // compute-side swizzled offsets (loop-invariant parts hoisted)
    const int bn_row = wcol * 32 + (lane & 7) + ((lane >> 4) << 3);
    const int b_c2   = (lane >> 3) & 1;
    const int ar_row = wrow * 32 + (lane & 15);
    const int a_c2   = lane >> 4;

    auto compute_ks = [&](uint32_t stb, int ks) {
        uint32_t bh[8], bl[8];
        #pragma unroll
        for (int p = 0; p < 2; ++p) {
            uint32_t off = swz(bn_row + p * 16, ks * 2 + b_c2);
            ldsm4(&bh[p * 4], stb + BHI_O + off);
            ldsm4(&bl[p * 4], stb + BLO_O + off);
        }
        #pragma unroll
        for (int mt = 0; mt < 2; ++mt) {
            uint32_t off = swz(ar_row + mt * 16, ks * 2 + a_c2);
            uint32_t ah[4], al[4];
            ldsm4(ah, stb + AHI_O + off);
            ldsm4(al, stb + ALO_O + off);
            #pragma unroll
            for (int nt = 0; nt < 4; ++nt) {
                if (nt < live_nt) {
                    mma_bf16(acc[mt][nt], ah, &bh[nt * 2]);
                    mma_bf16(acc[mt][nt], ah, &bl[nt * 2]);
                    mma_bf16(acc[mt][nt], al, &bh[nt * 2]);
                }
            }
        }
    };

    // prologue: chunks 0,1 into stages 0,1
    load_chunk(0, 0); CP_COMMIT();
    load_chunk(1, 1); CP_COMMIT();

    #pragma unroll
    for (int c = 0; c < NCH; ++c) {
        CP_WAIT1();            // chunk c's group complete (<=1 pending)
        __syncthreads();       // chunk c visible; compute(c-1) done everywhere

        const uint32_t stb = sb + (c % 3) * ST_SZ;   // compile-time under full unroll
        if (2 * c < NKS) compute_ks(stb, 0);         // mma ramp right after barrier

        if (c + 2 < NCH) load_chunk(c + 2, (c + 2) % 3);
        CP_COMMIT();           // uniform group counting

        if (2 * c + 1 < NKS) compute_ks(stb, 1);     // skip all-zero trailing ks block
    }

    // ---- store ----
    #pragma unroll
    for (int mt = 0; mt < 2; ++mt) {
        int r0 = row0 + wrow * 32 + mt * 16 + (lane >> 2);
        int r1 = r0 + 8;
        #pragma unroll
        for (int nt = 0; nt < 4; ++nt) {
            int col = col0 + wcol * 32 + nt * 8 + (lane & 3) * 2;
            if (OUT_BF16) {
                if (col < NN) {
                    float b0 = bias[col], b1 = bias[col + 1];
                    float v00 = fmaxf(acc[mt][nt][0] + b0, 0.f);
                    float v01 = fmaxf(acc[mt][nt][1] + b1, 0.f);
                    float v10 = fmaxf(acc[mt][nt][2] + b0, 0.f);
                    float v11 = fmaxf(acc[mt][nt][3] + b1, 0.f);
                    __nv_bfloat16 h0, l0, h1, l1;
                    split_bf16(v00, h0, l0); split_bf16(v01, h1, l1);
                    *(uint32_t*)(Ch + (size_t)r0 * SC + col) = pack_us(h0, h1);
                    *(uint32_t*)(Cl + (size_t)r0 * SC + col) = pack_us(l0, l1);
                    split_bf16(v10, h0, l0); split_bf16(v11, h1, l1);
                    *(uint32_t*)(Ch + (size_t)r1 * SC + col) = pack_us(h0, h1);
                    *(uint32_t*)(Cl + (size_t)r1 * SC + col) = pack_us(l0, l1);
                }
            } else {
                float b0 = (col < NBIAS) ? bias[col] : 0.f;
                float b1 = (col + 1 < NBIAS) ? bias[col + 1] : 0.f;
                float2 p0 = make_float2(acc[mt][nt][0] + b0, acc[mt][nt][1] + b1);
                float2 p1 = make_float2(acc[mt][nt][2] + b0, acc[mt][nt][3] + b1);
                *(float2*)(Cf + (size_t)r0 * SC + col) = p0;
                *(float2*)(Cf + (size_t)r1 * SC + col) = p1;
            }
        }
    }
}

// ---------------- math epilogue (v2: smem-staged coalesced row loads) ----------------
__device__ __forceinline__ float fast_tanh(float x)
{
    float ax = fabsf(x);
    float e  = __expf(-2.f * ax);
    float t  = __fdividef(1.f - e, 1.f + e);
    return copysignf(t, x);
}

__global__ __launch_bounds__(256)
void epilogue_kernel(const float* __restrict__ z3, const float* __restrict__ eps,
                     float* __restrict__ out)
{
    __shared__ float sL[8][256];

    int warp  = threadIdx.x >> 5;
    int lane  = threadIdx.x & 31;
    int gwarp = blockIdx.x * 8 + warp;   // one row per warp

    // coalesced stage: 256 floats per row via 2 float4 loads per lane
    {
        const float4* src = (const float4*)(z3 + (size_t)gwarp * 256);
        float4* dst = (float4*)&sL[warp][0];
        dst[lane]      = src[lane];
        dst[lane + 32] = src[lane + 32];
    }
    __syncwarp();

    const float* L = &sL[warp][0];
    float term_ttl = 0.f, term_eps = 0.f, corr = 0.f;

    if (lane < A_D) {
        int a = lane;
        float mw[M_D], mm[M_D], lms[M_D];
        #pragma unroll
        for (int m = 0; m < M_D; m++) {
            mw[m]  = fast_tanh(L[a * M_D + m]);
            mm[m]  = fast_tanh(L[85 + a * M_D + m]);
            lms[m] = fast_tanh(L[170 + a * M_D + m]);
        }
        float mx = mw[0];
        #pragma unroll
        for (int m = 1; m < M_D; m++) mx = fmaxf(mx, mw[m]);
        float e[M_D], se = 0.f;
        #pragma unroll
        for (int m = 0; m < M_D; m++) { e[m] = __expf(mw[m] - mx); se += e[m]; }
        float inv = __fdividef(1.f, se);

        float mean = 0.f, alea = 0.f;
        float w[M_D];
        #pragma unroll
        for (int m = 0; m < M_D; m++) {
            w[m]  = e[m] * inv;
            mean += w[m] * mm[m];
            float lc = fminf(fmaxf(lms[m], -10.f), 2.f);
            alea += w[m] * __expf(lc);
        }
        float epis = 0.f;
        #pragma unroll
        for (int m = 0; m < M_D; m++) {
            float dd = mm[m] - mean;
            epis += w[m] * dd * dd;
        }
        epis = fminf(fmaxf(epis, EPIS_MIN), EPIS_MAX);
        float total = alea + epis;

        float ev = eps[(size_t)gwarp * A_D + a];
        float x  = mean + total * ev;
        float th = fast_tanh(x);
        out[(size_t)gwarp * A_D + a] = th;

        float d  = x - mean;
        float zt = __fdividef(d, total);
        float ze = __fdividef(d, epis);
        term_ttl = zt * zt + 2.f * __logf(total);
        term_eps = ze * ze + 2.f * __logf(epis);
        corr     = __logf(1.f - th * th + 1e-6f);
    }

    #pragma unroll
    for (int off = 16; off > 0; off >>= 1) {
        term_ttl += __shfl_down_sync(0xffffffffu, term_ttl, off);
        term_eps += __shfl_down_sync(0xffffffffu, term_eps, off);
        corr     += __shfl_down_sync(0xffffffffu, corr, off);
    }

    if (lane == 0) {
        float lp_ttl = -0.5f * term_ttl - HALF_D_LOG2PI;
        float lp_eps = -0.5f * term_eps - HALF_D_LOG2PI;
        out[(size_t)NB * A_D + gwarp]       = lp_ttl - corr;
        out[(size_t)NB * (A_D + 1) + gwarp] = lp_eps - corr;
    }
}

// ---------------- launch ----------------
extern "C" void kernel_launch(void* const* d_in, const int* in_sizes, int n_in,
                              void* d_out, int out_size)
{
    (void)in_sizes; (void)n_in; (void)out_size;
    const float* state = (const float*)d_in[0];
    const float* eps   = (const float*)d_in[1];
    const float* W1    = (const float*)d_in[2];
    const float* b1    = (const float*)d_in[3];
    const float* W2    = (const float*)d_in[4];
    const float* b2    = (const float*)d_in[5];
    const float* W3    = (const float*)d_in[6];
    const float* b3    = (const float*)d_in[7];
    float* out = (float*)d_out;

    void *p;
    cudaGetSymbolAddress(&p, g_shi);  __nv_bfloat16* shh = (__nv_bfloat16*)p;
    cudaGetSymbolAddress(&p, g_slo);  __nv_bfloat16* shl = (__nv_bfloat16*)p;
    cudaGetSymbolAddress(&p, g_h1hi); __nv_bfloat16* h1h = (__nv_bfloat16*)p;
    cudaGetSymbolAddress(&p, g_h1lo); __nv_bfloat16* h1l = (__nv_bfloat16*)p;
    cudaGetSymbolAddress(&p, g_h2hi); __nv_bfloat16* h2h = (__nv_bfloat16*)p;
    cudaGetSymbolAddress(&p, g_h2lo); __nv_bfloat16* h2l = (__nv_bfloat16*)p;
    cudaGetSymbolAddress(&p, g_z3);   float* z3 = (float*)p;
    cudaGetSymbolAddress(&p, g_w1hi); __nv_bfloat16* w1h = (__nv_bfloat16*)p;
    cudaGetSymbolAddress(&p, g_w1lo); __nv_bfloat16* w1l = (__nv_bfloat16*)p;
    cudaGetSymbolAddress(&p, g_w2hi); __nv_bfloat16* w2h = (__nv_bfloat16*)p;
    cudaGetSymbolAddress(&p, g_w2lo); __nv_bfloat16* w2l = (__nv_bfloat16*)p;
    cudaGetSymbolAddress(&p, g_w3hi); __nv_bfloat16* w3h = (__nv_bfloat16*)p;
    cudaGetSymbolAddress(&p, g_w3lo); __nv_bfloat16* w3l = (__nv_bfloat16*)p;

    auto g1 = mma_gemm<1, 12, 24, N1, N1, K2P>;   // K=376 -> 24 live ks of 24
    auto g2 = mma_gemm<1, 13, 25, N2, N2, K3P>;   // K=400 -> 25 live ks of 26
    auto g3 = mma_gemm<0, 10, 19, 256, 255, 256>; // K=300 -> 19 live ks of 20
    cudaFuncSetAttribute(g1, cudaFuncAttributeMaxDynamicSharedMemorySize, SMEM_TOT);
    cudaFuncSetAttribute(g2, cudaFuncAttributeMaxDynamicSharedMemorySize, SMEM_TOT);
    cudaFuncSetAttribute(g3, cudaFuncAttributeMaxDynamicSharedMemorySize, SMEM_TOT);

    dim3 blk(256);
    int wtot = W1_TOT + W2_TOT + W3_TOT;
    split_w_all<<<(wtot + 255) / 256, 256>>>(W1, W2, W3, w1h, w1l, w2h, w2l, w3h, w3l);
    split_act<<<((size_t)NB * K1P / 4 + 255) / 256, 256>>>(state, shh, shl);

    // index 3 = g2 for ncu visibility
    g1<<<dim3(7, NB/128), blk, SMEM_TOT>>>(shh, shl, w1h, w1l, b1, nullptr, h1h, h1l);
    g2<<<dim3(5, NB/128), blk, SMEM_TOT>>>(h1h, h1l, w2h, w2l, b2, nullptr, h2h, h2l);
    g3<<<dim3(4, NB/128), blk, SMEM_TOT>>>(h2h, h2l, w3h, w3l, b3, z3, nullptr, nullptr);

    epilogue_kernel<<<NB/8, 256>>>(z3, eps, out);
}

// round 15
// speedup vs baseline: 1.2161x; 1.0457x over previous
#include <cuda_runtime.h>
#include <cuda_bf16.h>
#include <math.h>
#include <stdint.h>

// ---------------- problem dims ----------------
#define NB   131072
#define A_D  17
#define M_D  5

#define K1   376      // state dim
#define N1   400
#define N2   300
#define K1P  384      // state pad: 12 chunks of 32
#define H1P  448      // h1 stride: 7 full 64-col tiles (and g2's padded K)
#define H2P  320      // h2 stride: 5 full tiles (and g3's padded K)

#define EPIS_MIN 4.53999297624848e-05f
#define EPIS_MAX 7.38905609893065f
#define HALF_D_LOG2PI 15.6219550644794f

// ---------------- scratch (__device__ globals; zero-initialized at load) ----------------
__device__ __align__(16) __nv_bfloat16 g_shi[(size_t)NB * K1P];
__device__ __align__(16) __nv_bfloat16 g_slo[(size_t)NB * K1P];
__device__ __align__(16) __nv_bfloat16 g_h1hi[(size_t)NB * H1P];
__device__ __align__(16) __nv_bfloat16 g_h1lo[(size_t)NB * H1P];
__device__ __align__(16) __nv_bfloat16 g_h2hi[(size_t)NB * H2P];
__device__ __align__(16) __nv_bfloat16 g_h2lo[(size_t)NB * H2P];
__device__ __align__(16) float g_z3[(size_t)NB * 256];

// weights, transposed + split: [N_alloc][K_pad], zero-padded (rows n>=N zeroed)
__device__ __align__(16) __nv_bfloat16 g_w1hi[512 * K1P], g_w1lo[512 * K1P];
__device__ __align__(16) __nv_bfloat16 g_w2hi[384 * H1P], g_w2lo[384 * H1P];
__device__ __align__(16) __nv_bfloat16 g_w3hi[256 * H2P], g_w3lo[256 * H2P];

// zero-padded biases (unguarded reads in FULL tiles)
__device__ float g_b1p[H1P];
__device__ float g_b2p[H2P];
__device__ float g_b3p[256];

#define W1_TOT (512 * K1P)
#define W2_TOT (384 * H1P)
#define W3_TOT (256 * H2P)
#define B_TOT  (H1P + H2P + 256)

// ---------------- helpers ----------------
__device__ __forceinline__ uint32_t smem_u32(const void* p) {
    uint32_t a;
    asm("{ .reg .u64 t; cvta.to.shared.u64 t, %1; cvt.u32.u64 %0, t; }" : "=r"(a) : "l"(p));
    return a;
}

__device__ __forceinline__ void ldsm4(uint32_t* r, uint32_t addr) {
    asm volatile("ldmatrix.sync.aligned.m8n8.x4.shared.b16 {%0,%1,%2,%3}, [%4];"
                 : "=r"(r[0]), "=r"(r[1]), "=r"(r[2]), "=r"(r[3]) : "r"(addr));
}

__device__ __forceinline__ void mma_bf16(float* c, const uint32_t* a, const uint32_t* b) {
    asm volatile("mma.sync.aligned.m16n8k16.row.col.f32.bf16.bf16.f32 "
                 "{%0,%1,%2,%3}, {%4,%5,%6,%7}, {%8,%9}, {%0,%1,%2,%3};"
                 : "+f"(c[0]), "+f"(c[1]), "+f"(c[2]), "+f"(c[3])
                 : "r"(a[0]), "r"(a[1]), "r"(a[2]), "r"(a[3]), "r"(b[0]), "r"(b[1]));
}

__device__ __forceinline__ void cp16(uint32_t dst, const void* src) {
    asm volatile("cp.async.cg.shared.global [%0], [%1], 16;"
                 :: "r"(dst), "l"(src) : "memory");
}
#define CP_COMMIT() asm volatile("cp.async.commit_group;" ::: "memory")
#define CP_WAIT1()  asm volatile("cp.async.wait_group 1;" ::: "memory")

__device__ __forceinline__ void split_bf16(float x, __nv_bfloat16& h, __nv_bfloat16& l) {
    h = __float2bfloat16_rn(x);
    l = __float2bfloat16_rn(x - __bfloat162float(h));
}
__device__ __forceinline__ uint32_t pack_us(__nv_bfloat16 a, __nv_bfloat16 b) {
    return (uint32_t)__bfloat16_as_ushort(a) | ((uint32_t)__bfloat16_as_ushort(b) << 16);
}

// XOR swizzle: 16B chunk c (0..3) of row r at phys chunk c ^ ((r>>1)&3); 64B pitch.
__device__ __forceinline__ uint32_t swz(int r, int c) {
    return (uint32_t)(r * 64 + ((c ^ ((r >> 1) & 3)) << 4));
}

// ---------------- prep: weights (transpose + split) and padded biases ----------------
__global__ void split_w_all(const float* __restrict__ W1, const float* __restrict__ W2,
                            const float* __restrict__ W3,
                            const float* __restrict__ b1, const float* __restrict__ b2,
                            const float* __restrict__ b3,
                            __nv_bfloat16* __restrict__ w1h, __nv_bfloat16* __restrict__ w1l,
                            __nv_bfloat16* __restrict__ w2h, __nv_bfloat16* __restrict__ w2l,
                            __nv_bfloat16* __restrict__ w3h, __nv_bfloat16* __restrict__ w3l,
                            float* __restrict__ b1p, float* __restrict__ b2p,
                            float* __restrict__ b3p)
{
    int idx = blockIdx.x * blockDim.x + threadIdx.x;
    if (idx >= W1_TOT + W2_TOT + W3_TOT) {
        int bi = idx - (W1_TOT + W2_TOT + W3_TOT);
        if (bi < H1P)                 b1p[bi] = (bi < N1) ? b1[bi] : 0.f;
        else if (bi < H1P + H2P)      { int j = bi - H1P; b2p[j] = (j < N2) ? b2[j] : 0.f; }
        else if (bi < B_TOT)          { int j = bi - H1P - H2P; b3p[j] = (j < 255) ? b3[j] : 0.f; }
        return;
    }
    const float* W; __nv_bfloat16 *Hh, *Hl;
    int K, N, Kp, loc;
    if (idx < W1_TOT) {
        W = W1; Hh = w1h; Hl = w1l; K = K1; N = N1; Kp = K1P; loc = idx;
    } else if (idx < W1_TOT + W2_TOT) {
        W = W2; Hh = w2h; Hl = w2l; K = N1; N = N2; Kp = H1P; loc = idx - W1_TOT;
    } else {
        W = W3; Hh = w3h; Hl = w3l; K = N2; N = 255; Kp = H2P; loc = idx - W1_TOT - W2_TOT;
    }
    int n = loc / Kp;
    int k = loc - n * Kp;
    float v = (k < K && n < N) ? W[(size_t)k * N + n] : 0.f;
    __nv_bfloat16 h, l;
    split_bf16(v, h, l);
    Hh[loc] = h;
    Hl[loc] = l;
}

// ---------------- activation prep: fp32 state -> bf16 hi/lo, zero-padded ----------------
__global__ void split_act(const float* __restrict__ X, __nv_bfloat16* __restrict__ Hh,
                          __nv_bfloat16* __restrict__ Hl)
{
    int idx = blockIdx.x * blockDim.x + threadIdx.x;   // one per 4 elements
    size_t i4 = (size_t)idx * 4;
    if (i4 >= (size_t)NB * K1P) return;
    int row = (int)(i4 / K1P);
    int k   = (int)(i4 - (size_t)row * K1P);
    uint2 hw = make_uint2(0u, 0u), lw = hw;
    if (k < K1) {   // K1 % 4 == 0, so full float4 or none
        float4 v = *(const float4*)(X + (size_t)row * K1 + k);
        __nv_bfloat16 h0,l0,h1,l1,h2,l2,h3,l3;
        split_bf16(v.x,h0,l0); split_bf16(v.y,h1,l1);
        split_bf16(v.z,h2,l2); split_bf16(v.w,h3,l3);
        hw.x = pack_us(h0,h1); hw.y = pack_us(h2,h3);
        lw.x = pack_us(l0,l1); lw.y = pack_us(l2,l3);
    }
    *(uint2*)(Hh + i4) = hw;
    *(uint2*)(Hl + i4) = lw;
}

// ---------------- bf16x3 mma GEMM (FULL tiles, no predicates) ----------------
// BM=128, BN=64, BK=32; 8 warps as 4(row)x2(col); warp tile 32x32.
// 3-stage cp.async pipeline (lookahead 2), XOR-swizzled 64B-pitch smem.
// Output space padded so every tile is full: no column predicates, no store guards.
// KPAD = row stride of A and B (may exceed NCH*32). NKS trims dead ks blocks.
#define AHI_O  0
#define ALO_O  8192
#define BHI_O  16384
#define BLO_O  20480
#define ST_SZ  24576
#define SMEM_TOT (3 * ST_SZ)

template<int OUT_BF16, int NCH, int NKS, int KPAD, int SC>
__global__ __launch_bounds__(256, 3)
void mma_gemm(const __nv_bfloat16* __restrict__ Ah, const __nv_bfloat16* __restrict__ Al,
              const __nv_bfloat16* __restrict__ Bh, const __nv_bfloat16* __restrict__ Bl,
              const float* __restrict__ bias,
              float* __restrict__ Cf, __nv_bfloat16* __restrict__ Ch, __nv_bfloat16* __restrict__ Cl)
{
    extern __shared__ char smem[];
    const uint32_t sb = smem_u32(smem);
    const int tid  = threadIdx.x;
    const int lane = tid & 31;
    const int wid  = tid >> 5;
    const int wrow = wid & 3;        // 0..3 : 32-row group
    const int wcol = wid >> 2;       // 0..1 : 32-col group
    const int row0 = blockIdx.y * 128;
    const int col0 = blockIdx.x * 64;

    float acc[2][4][4];
    #pragma unroll
    for (int i = 0; i < 2; i++)
        #pragma unroll
        for (int j = 0; j < 4; j++)
            #pragma unroll
            for (int q = 0; q < 4; q++) acc[i][j][q] = 0.f;

    // loader base pointers (chunk offset is a compile-time immediate per unroll step)
    const int arow = tid >> 1;
    const int ahf  = tid & 1;
    const int brow = tid >> 2;
    const int bq   = tid & 3;
    const __nv_bfloat16* pAh = Ah + (size_t)(row0 + arow) * KPAD + ahf * 16;
    const __nv_bfloat16* pAl = Al + (size_t)(row0 + arow) * KPAD + ahf * 16;
    const __nv_bfloat16* pBh = Bh + (size_t)(col0 + brow) * KPAD + bq * 8;
    const __nv_bfloat16* pBl = Bl + (size_t)(col0 + brow) * KPAD + bq * 8;
    const uint32_t sa0 = swz(arow, ahf * 2);
    const uint32_t sa1 = swz(arow, ahf * 2 + 1);
    const uint32_t sb0 = swz(brow, bq);

    auto load_chunk = [&](int c, int s) {
        const uint32_t stb = sb + s * ST_SZ;
        cp16(stb + sa0 + AHI_O, pAh + c * 32);
        cp16(stb + sa1 + AHI_O, pAh + c * 32 + 8);
        cp16(stb + sa0 + ALO_O, pAl + c * 32);
        cp16(stb + sa1 + ALO_O, pAl + c * 32 + 8);
        cp16(stb + sb0 + BHI_O, pBh + c * 32);
        cp16(stb + sb0 + BLO_O, pBl + c * 32);
    };

    // compute-side swizzled offsets (loop-invariant parts hoisted)
    const int bn_row = wcol * 32 + (lane & 7) + ((lane >> 4) << 3);
    const int b_c2   = (lane >> 3) & 1;
    const int ar_row = wrow * 32 + (lane & 15);
    const int a_c2   = lane >> 4;

    auto compute_ks = [&](uint32_t stb, int ks) {
        uint32_t bh[8], bl[8];
        #pragma unroll
        for (int p = 0; p < 2; ++p) {
            uint32_t off = swz(bn_row + p * 16, ks * 2 + b_c2);
            ldsm4(&bh[p * 4], stb + BHI_O + off);
            ldsm4(&bl[p * 4], stb + BLO_O + off);
        }
        #pragma unroll
        for (int mt = 0; mt < 2; ++mt) {
            uint32_t off = swz(ar_row + mt * 16, ks * 2 + a_c2);
            uint32_t ah[4], al[4];
            ldsm4(ah, stb + AHI_O + off);
            ldsm4(al, stb + ALO_O + off);
            #pragma unroll
            for (int nt = 0; nt < 4; ++nt) {
                mma_bf16(acc[mt][nt], ah, &bh[nt * 2]);
                mma_bf16(acc[mt][nt], ah, &bl[nt * 2]);
                mma_bf16(acc[mt][nt], al, &bh[nt * 2]);
            }
        }
    };

    // prologue: chunks 0,1 into stages 0,1
    load_chunk(0, 0); CP_COMMIT();
    load_chunk(1, 1); CP_COMMIT();

    #pragma unroll
    for (int c = 0; c < NCH; ++c) {
        CP_WAIT1();            // chunk c's group complete (<=1 pending)
        __syncthreads();       // chunk c visible; compute(c-1) done everywhere

        const uint32_t stb = sb + (c % 3) * ST_SZ;   // compile-time under full unroll
        if (2 * c < NKS) compute_ks(stb, 0);         // mma ramp right after barrier

        if (c + 2 < NCH) load_chunk(c + 2, (c + 2) % 3);
        CP_COMMIT();           // uniform group counting

        if (2 * c + 1 < NKS) compute_ks(stb, 1);     // skip all-zero trailing ks block
    }

    // ---- store (unguarded: all tiles full, biases zero-padded) ----
    #pragma unroll
    for (int mt = 0; mt < 2; ++mt) {
        int r0 = row0 + wrow * 32 + mt * 16 + (lane >> 2);
        int r1 = r0 + 8;
        #pragma unroll
        for (int nt = 0; nt < 4; ++nt) {
            int col = col0 + wcol * 32 + nt * 8 + (lane & 3) * 2;
            float b0 = bias[col], b1 = bias[col + 1];
            if (OUT_BF16) {
                float v00 = fmaxf(acc[mt][nt][0] + b0, 0.f);
                float v01 = fmaxf(acc[mt][nt][1] + b1, 0.f);
                float v10 = fmaxf(acc[mt][nt][2] + b0, 0.f);
                float v11 = fmaxf(acc[mt][nt][3] + b1, 0.f);
                __nv_bfloat16 h0, l0, h1, l1;
                split_bf16(v00, h0, l0); split_bf16(v01, h1, l1);
                *(uint32_t*)(Ch + (size_t)r0 * SC + col) = pack_us(h0, h1);
                *(uint32_t*)(Cl + (size_t)r0 * SC + col) = pack_us(l0, l1);
                split_bf16(v10, h0, l0); split_bf16(v11, h1, l1);
                *(uint32_t*)(Ch + (size_t)r1 * SC + col) = pack_us(h0, h1);
                *(uint32_t*)(Cl + (size_t)r1 * SC + col) = pack_us(l0, l1);
            } else {
                float2 p0 = make_float2(acc[mt][nt][0] + b0, acc[mt][nt][1] + b1);
                float2 p1 = make_float2(acc[mt][nt][2] + b0, acc[mt][nt][3] + b1);
                *(float2*)(Cf + (size_t)r0 * SC + col) = p0;
                *(float2*)(Cf + (size_t)r1 * SC + col) = p1;
            }
        }
    }
}

// ---------------- math epilogue (smem-staged coalesced row loads) ----------------
__device__ __forceinline__ float fast_tanh(float x)
{
    float ax = fabsf(x);
    float e  = __expf(-2.f * ax);
    float t  = __fdividef(1.f - e, 1.f + e);
    return copysignf(t, x);
}

__global__ __launch_bounds__(256)
void epilogue_kernel(const float* __restrict__ z3, const float* __restrict__ eps,
                     float* __restrict__ out)
{
    __shared__ float sL[8][256];

    int warp  = threadIdx.x >> 5;
    int lane  = threadIdx.x & 31;
    int gwarp = blockIdx.x * 8 + warp;   // one row per warp

    {
        const float4* src = (const float4*)(z3 + (size_t)gwarp * 256);
        float4* dst = (float4*)&sL[warp][0];
        dst[lane]      = src[lane];
        dst[lane + 32] = src[lane + 32];
    }
    __syncwarp();

    const float* L = &sL[warp][0];
    float term_ttl = 0.f, term_eps = 0.f, corr = 0.f;

    if (lane < A_D) {
        int a = lane;
        float mw[M_D], mm[M_D], lms[M_D];
        #pragma unroll
        for (int m = 0; m < M_D; m++) {
            mw[m]  = fast_tanh(L[a * M_D + m]);
            mm[m]  = fast_tanh(L[85 + a * M_D + m]);
            lms[m] = fast_tanh(L[170 + a * M_D + m]);
        }
        float mx = mw[0];
        #pragma unroll
        for (int m = 1; m < M_D; m++) mx = fmaxf(mx, mw[m]);
        float e[M_D], se = 0.f;
        #pragma unroll
        for (int m = 0; m < M_D; m++) { e[m] = __expf(mw[m] - mx); se += e[m]; }
        float inv = __fdividef(1.f, se);

        float mean = 0.f, alea = 0.f;
        float w[M_D];
        #pragma unroll
        for (int m = 0; m < M_D; m++) {
            w[m]  = e[m] * inv;
            mean += w[m] * mm[m];
            float lc = fminf(fmaxf(lms[m], -10.f), 2.f);
            alea += w[m] * __expf(lc);
        }
        float epis = 0.f;
        #pragma unroll
        for (int m = 0; m < M_D; m++) {
            float dd = mm[m] - mean;
            epis += w[m] * dd * dd;
        }
        epis = fminf(fmaxf(epis, EPIS_MIN), EPIS_MAX);
        float total = alea + epis;

        float ev = eps[(size_t)gwarp * A_D + a];
        float x  = mean + total * ev;
        float th = fast_tanh(x);
        out[(size_t)gwarp * A_D + a] = th;

        float d  = x - mean;
        float zt = __fdividef(d, total);
        float ze = __fdividef(d, epis);
        term_ttl = zt * zt + 2.f * __logf(total);
        term_eps = ze * ze + 2.f * __logf(epis);
        corr     = __logf(1.f - th * th + 1e-6f);
    }

    #pragma unroll
    for (int off = 16; off > 0; off >>= 1) {
        term_ttl += __shfl_down_sync(0xffffffffu, term_ttl, off);
        term_eps += __shfl_down_sync(0xffffffffu, term_eps, off);
        corr     += __shfl_down_sync(0xffffffffu, corr, off);
    }

    if (lane == 0) {
        float lp_ttl = -0.5f * term_ttl - HALF_D_LOG2PI;
        float lp_eps = -0.5f * term_eps - HALF_D_LOG2PI;
        out[(size_t)NB * A_D + gwarp]       = lp_ttl - corr;
        out[(size_t)NB * (A_D + 1) + gwarp] = lp_eps - corr;
    }
}

// ---------------- launch ----------------
extern "C" void kernel_launch(void* const* d_in, const int* in_sizes, int n_in,
                              void* d_out, int out_size)
{
    (void)in_sizes; (void)n_in; (void)out_size;
    const float* state = (const float*)d_in[0];
    const float* eps   = (const float*)d_in[1];
    const float* W1    = (const float*)d_in[2];
    const float* b1    = (const float*)d_in[3];
    const float* W2    = (const float*)d_in[4];
    const float* b2    = (const float*)d_in[5];
    const float* W3    = (const float*)d_in[6];
    const float* b3    = (const float*)d_in[7];
    float* out = (float*)d_out;

    void *p;
    cudaGetSymbolAddress(&p, g_shi);  __nv_bfloat16* shh = (__nv_bfloat16*)p;
    cudaGetSymbolAddress(&p, g_slo);  __nv_bfloat16* shl = (__nv_bfloat16*)p;
    cudaGetSymbolAddress(&p, g_h1hi); __nv_bfloat16* h1h = (__nv_bfloat16*)p;
    cudaGetSymbolAddress(&p, g_h1lo); __nv_bfloat16* h1l = (__nv_bfloat16*)p;
    cudaGetSymbolAddress(&p, g_h2hi); __nv_bfloat16* h2h = (__nv_bfloat16*)p;
    cudaGetSymbolAddress(&p, g_h2lo); __nv_bfloat16* h2l = (__nv_bfloat16*)p;
    cudaGetSymbolAddress(&p, g_z3);   float* z3 = (float*)p;
    cudaGetSymbolAddress(&p, g_w1hi); __nv_bfloat16* w1h = (__nv_bfloat16*)p;
    cudaGetSymbolAddress(&p, g_w1lo); __nv_bfloat16* w1l = (__nv_bfloat16*)p;
    cudaGetSymbolAddress(&p, g_w2hi); __nv_bfloat16* w2h = (__nv_bfloat16*)p;
    cudaGetSymbolAddress(&p, g_w2lo); __nv_bfloat16* w2l = (__nv_bfloat16*)p;
    cudaGetSymbolAddress(&p, g_w3hi); __nv_bfloat16* w3h = (__nv_bfloat16*)p;
    cudaGetSymbolAddress(&p, g_w3lo); __nv_bfloat16* w3l = (__nv_bfloat16*)p;
    float *b1p, *b2p, *b3p;
    cudaGetSymbolAddress(&p, g_b1p); b1p = (float*)p;
    cudaGetSymbolAddress(&p, g_b2p); b2p = (float*)p;
    cudaGetSymbolAddress(&p, g_b3p); b3p = (float*)p;

    // g1: K=376 (12 chunks over K1P=384), NKS=24; out stride H1P=448, 7 full tiles
    auto g1 = mma_gemm<1, 12, 24, K1P, H1P>;
    // g2: K=400 (13 chunks over H1P=448 stride), NKS=25; out stride H2P=320, 5 full tiles
    auto g2 = mma_gemm<1, 13, 25, H1P, H2P>;
    // g3: K=300 (10 chunks over H2P=320), NKS=19; out fp32 stride 256, 4 full tiles
    auto g3 = mma_gemm<0, 10, 19, H2P, 256>;
    cudaFuncSetAttribute(g1, cudaFuncAttributeMaxDynamicSharedMemorySize, SMEM_TOT);
    cudaFuncSetAttribute(g2, cudaFuncAttributeMaxDynamicSharedMemorySize, SMEM_TOT);
    cudaFuncSetAttribute(g3, cudaFuncAttributeMaxDynamicSharedMemorySize, SMEM_TOT);

    dim3 blk(256);
    int ptot = W1_TOT + W2_TOT + W3_TOT + B_TOT;
    split_w_all<<<(ptot + 255) / 256, 256>>>(W1, W2, W3, b1, b2, b3,
                                             w1h, w1l, w2h, w2l, w3h, w3l,
                                             b1p, b2p, b3p);
    split_act<<<((size_t)NB * K1P / 4 + 255) / 256, 256>>>(state, shh, shl);

    // index 3 = g2 for ncu visibility
    g1<<<dim3(7, NB/128), blk, SMEM_TOT>>>(shh, shl, w1h, w1l, b1p, nullptr, h1h, h1l);
    g2<<<dim3(5, NB/128), blk, SMEM_TOT>>>(h1h, h1l, w2h, w2l, b2p, nullptr, h2h, h2l);
    g3<<<dim3(4, NB/128), blk, SMEM_TOT>>>(h2h, h2l, w3h, w3l, b3p, z3, nullptr, nullptr);

    epilogue_kernel<<<NB/8, 256>>>(z3, eps, out);
}